// round 7
// baseline (speedup 1.0000x reference)
#include <cuda_runtime.h>
#include <cuda_fp16.h>
#include <cstdint>
#include <cstddef>

// ---------------------------------------------------------------------------
// out = sigmoid(relu(x @ W1 + b1) @ W2 + b2)
// fp16 mma.sync (HMMA) GEMMs, fp32 accum.
// 4 warps/CTA (2x2), warp tile 64x64; 3-stage cp.async pipeline with a single
// __syncthreads() per K-iteration.
// (tcgen05 unavailable: harness PTX targets base sm_103, not sm_103a)
// ---------------------------------------------------------------------------

#define DI __device__ __forceinline__

static constexpr int BATCH = 4096;
static constexpr int IN_F  = 2048;
static constexpr int HID_F = 8192;
static constexpr int OUT_F = 2048;

__device__ __align__(16) __half g_x  [(size_t)BATCH * IN_F];   // A of GEMM1 [M,K]
__device__ __align__(16) __half g_w1t[(size_t)HID_F * IN_F];   // B of GEMM1 [N,K]
__device__ __align__(16) __half g_w2t[(size_t)OUT_F * HID_F];  // B of GEMM2 [N,K]
__device__ __align__(16) __half g_h  [(size_t)BATCH * HID_F];  // A of GEMM2 [M,K]

// ---------------------------------------------------------------------------
DI uint32_t smem_u32(const void* p) {
    uint32_t a;
    asm("{ .reg .u64 t; cvta.to.shared.u64 t, %1; cvt.u32.u64 %0, t; }"
        : "=r"(a) : "l"(p));
    return a;
}

DI void cp_async16(uint32_t dst, const void* src) {
    asm volatile("cp.async.cg.shared.global [%0], [%1], 16;"
                 :: "r"(dst), "l"(src) : "memory");
}
DI void cp_commit() { asm volatile("cp.async.commit_group;" ::: "memory"); }
template <int N> DI void cp_wait() {
    asm volatile("cp.async.wait_group %0;" :: "n"(N) : "memory");
}

DI void ldm4(uint32_t* r, uint32_t addr) {
    asm volatile("ldmatrix.sync.aligned.m8n8.x4.shared.b16 {%0,%1,%2,%3}, [%4];"
                 : "=r"(r[0]), "=r"(r[1]), "=r"(r[2]), "=r"(r[3]) : "r"(addr));
}

DI void mma16816(float* d, const uint32_t* a, uint32_t b0, uint32_t b1) {
    asm volatile(
        "mma.sync.aligned.m16n8k16.row.col.f32.f16.f16.f32 "
        "{%0,%1,%2,%3}, {%4,%5,%6,%7}, {%8,%9}, {%0,%1,%2,%3};"
        : "+f"(d[0]), "+f"(d[1]), "+f"(d[2]), "+f"(d[3])
        : "r"(a[0]), "r"(a[1]), "r"(a[2]), "r"(a[3]), "r"(b0), "r"(b1));
}

DI uint32_t sw128(uint32_t o) { return o ^ ((o >> 3) & 0x70); }

// ---------------------------------------------------------------------------
// Prep kernels
// ---------------------------------------------------------------------------
__global__ void convert_x_kernel(const float* __restrict__ x) {
    size_t i = ((size_t)blockIdx.x * 256 + threadIdx.x) * 4;
    float4 v = *reinterpret_cast<const float4*>(x + i);
    __half2* dst = reinterpret_cast<__half2*>(&g_x[i]);
    dst[0] = __floats2half2_rn(v.x, v.y);
    dst[1] = __floats2half2_rn(v.z, v.w);
}

// W [K,N] f32 row-major -> Wt [N,K] fp16 row-major.  64x64 tiles, 256 threads.
template <int WHICH>
__global__ __launch_bounds__(256)
void transpose_kernel(const float* __restrict__ W) {
    constexpr int K = WHICH ? HID_F : IN_F;
    constexpr int N = WHICH ? OUT_F : HID_F;
    __half* Wt = WHICH ? g_w2t : g_w1t;
    __shared__ float tile[64][65];
    const int n0 = blockIdx.x * 64;
    const int k0 = blockIdx.y * 64;
    const int tid = threadIdx.x;
    const int r = tid >> 4;
    const int c = tid & 15;

#pragma unroll
    for (int j = 0; j < 4; ++j) {
        const int row = r + j * 16;
        float4 v = *reinterpret_cast<const float4*>(
            &W[(size_t)(k0 + row) * N + n0 + c * 4]);
        tile[row][c * 4 + 0] = v.x;
        tile[row][c * 4 + 1] = v.y;
        tile[row][c * 4 + 2] = v.z;
        tile[row][c * 4 + 3] = v.w;
    }
    __syncthreads();
#pragma unroll
    for (int j = 0; j < 4; ++j) {
        const int row = r + j * 16;
        __half h[4];
#pragma unroll
        for (int i = 0; i < 4; ++i)
            h[i] = __float2half(tile[c * 4 + i][row]);
        *reinterpret_cast<uint2*>(&Wt[(size_t)(n0 + row) * K + k0 + c * 4]) =
            *reinterpret_cast<const uint2*>(h);
    }
}

// ---------------------------------------------------------------------------
// GEMM: per-CTA 128x128, K-chunk 64, 3-stage cp.async pipeline, 1 sync/iter.
// 128 threads = 4 warps as 2(M) x 2(N); warp tile 64x64.
// ---------------------------------------------------------------------------
static constexpr int TILE_BYTES  = 128 * 128;          // 16 KB
static constexpr int STAGE_BYTES = 2 * TILE_BYTES;     // A + B = 32 KB
static constexpr int NSTAGE      = 3;
static constexpr int SMEM_DYN    = 1024 + NSTAGE * STAGE_BYTES;

DI void load_tile(uint32_t sdst, const char* g, size_t ldb, int tid) {
    // 128 rows x 128 bytes, 16B chunks, SW128 swizzle; 8 chunks/thread @128thr
#pragma unroll
    for (int i = 0; i < 8; ++i) {
        int idx = tid + i * 128;          // 0..1023
        int row = idx >> 3;
        int c   = idx & 7;
        uint32_t o = (uint32_t)(row * 128 + c * 16);
        cp_async16(sdst + sw128(o), g + (size_t)row * ldb + c * 16);
    }
}

template <int EPI>
__global__ __launch_bounds__(128, 2)
void gemm_kernel(const float* __restrict__ bias, float* __restrict__ out_f32) {
    constexpr int KDIM  = EPI ? HID_F : IN_F;
    constexpr int NITER = KDIM / 64;
    constexpr size_t LDB = (size_t)KDIM * 2;
    const __half* A = EPI ? g_h   : g_x;
    const __half* B = EPI ? g_w2t : g_w1t;

    extern __shared__ char smem_raw[];
    const uint32_t sbase = (smem_u32(smem_raw) + 1023) & ~1023u;

    const int tid  = threadIdx.x;
    const int lane = tid & 31;
    const int warp = tid >> 5;
    const int wm   = warp & 1;    // 2 warps along M (64 rows each)
    const int wn   = warp >> 1;   // 2 warps along N (64 cols each)
    const int mBase = blockIdx.y * 128;
    const int nBase = blockIdx.x * 128;

    const char* gA = (const char*)(A + (size_t)mBase * KDIM);
    const char* gB = (const char*)(B + (size_t)nBase * KDIM);

    float acc[4][8][4];   // [mt 16-rows][nt 8-cols][frag] = 128 regs
#pragma unroll
    for (int i = 0; i < 4; ++i)
#pragma unroll
        for (int j = 0; j < 8; ++j)
#pragma unroll
            for (int k = 0; k < 4; ++k) acc[i][j][k] = 0.0f;

    // prologue: stages 0 and 1 in flight
    load_tile(sbase,              gA, LDB, tid);
    load_tile(sbase + TILE_BYTES, gB, LDB, tid);
    cp_commit();
    {
        const uint32_t s1 = sbase + STAGE_BYTES;
        load_tile(s1,              gA + 128, LDB, tid);
        load_tile(s1 + TILE_BYTES, gB + 128, LDB, tid);
        cp_commit();
    }
    cp_wait<1>();        // stage 0 ready
    __syncthreads();

    const uint32_t aRowOff = (uint32_t)((wm * 64 + (lane & 15)) * 128 + ((lane >> 4) << 4));
    const uint32_t bRowOff = (uint32_t)((wn * 64 + (lane & 15)) * 128 + ((lane >> 4) << 4));

    int stage = 0;
#pragma unroll 1
    for (int it = 0; it < NITER; ++it) {
        // issue loads for stage it+2 (slot last read in iter it-1; synced since)
        if (it + 2 < NITER) {
            int ns = stage + 2; if (ns >= NSTAGE) ns -= NSTAGE;
            const uint32_t sNext = sbase + ns * STAGE_BYTES;
            const size_t kOff = (size_t)(it + 2) * 128;
            load_tile(sNext,              gA + kOff, LDB, tid);
            load_tile(sNext + TILE_BYTES, gB + kOff, LDB, tid);
            cp_commit();
        }

        // compute stage `stage` (ready per wait at end of previous iteration)
        const uint32_t As = sbase + stage * STAGE_BYTES;
        const uint32_t Bs = As + TILE_BYTES;
#pragma unroll
        for (int ks = 0; ks < 4; ++ks) {
            uint32_t a[4][4], b[4][4];
            const uint32_t koff = ks * 32;
#pragma unroll
            for (int mt = 0; mt < 4; ++mt)
                ldm4(a[mt], As + sw128(aRowOff + mt * 16 * 128 + koff));
#pragma unroll
            for (int nt2 = 0; nt2 < 4; ++nt2)
                ldm4(b[nt2], Bs + sw128(bRowOff + nt2 * 16 * 128 + koff));
#pragma unroll
            for (int mt = 0; mt < 4; ++mt)
#pragma unroll
                for (int nt = 0; nt < 8; ++nt) {
                    const uint32_t* bb = b[nt >> 1];
                    if (nt & 1) mma16816(acc[mt][nt], a[mt], bb[1], bb[3]);
                    else        mma16816(acc[mt][nt], a[mt], bb[0], bb[2]);
                }
        }

        // make stage it+1 visible before next iteration's compute
        if (it + 2 < NITER) cp_wait<1>(); else cp_wait<0>();
        __syncthreads();
        if (++stage == NSTAGE) stage = 0;
    }

    // epilogue
#pragma unroll
    for (int mt = 0; mt < 4; ++mt) {
#pragma unroll
        for (int nt = 0; nt < 8; ++nt) {
            const int col = nBase + wn * 64 + nt * 8 + (lane & 3) * 2;
            const float bv0 = __ldg(&bias[col]);
            const float bv1 = __ldg(&bias[col + 1]);
#pragma unroll
            for (int rr = 0; rr < 2; ++rr) {
                const int row = mBase + wm * 64 + mt * 16 + (lane >> 2) + rr * 8;
                float v0 = acc[mt][nt][rr * 2 + 0] + bv0;
                float v1 = acc[mt][nt][rr * 2 + 1] + bv1;
                if (EPI == 0) {
                    __half2 h = __floats2half2_rn(fmaxf(v0, 0.0f), fmaxf(v1, 0.0f));
                    *reinterpret_cast<__half2*>(&g_h[(size_t)row * HID_F + col]) = h;
                } else {
                    float2 o;
                    o.x = 1.0f / (1.0f + __expf(-v0));
                    o.y = 1.0f / (1.0f + __expf(-v1));
                    *reinterpret_cast<float2*>(&out_f32[(size_t)row * OUT_F + col]) = o;
                }
            }
        }
    }
}

// ---------------------------------------------------------------------------
extern "C" void kernel_launch(void* const* d_in, const int* in_sizes, int n_in,
                              void* d_out, int out_size) {
    (void)in_sizes; (void)n_in; (void)out_size;
    const float* x  = (const float*)d_in[0];
    const float* W1 = (const float*)d_in[1];
    const float* b1 = (const float*)d_in[2];
    const float* W2 = (const float*)d_in[3];
    const float* b2 = (const float*)d_in[4];
    float* out = (float*)d_out;

    cudaFuncSetAttribute(gemm_kernel<0>, cudaFuncAttributeMaxDynamicSharedMemorySize, SMEM_DYN);
    cudaFuncSetAttribute(gemm_kernel<1>, cudaFuncAttributeMaxDynamicSharedMemorySize, SMEM_DYN);

    convert_x_kernel<<<(BATCH * IN_F) / (256 * 4), 256>>>(x);
    transpose_kernel<0><<<dim3(HID_F / 64, IN_F / 64), 256>>>(W1);
    transpose_kernel<1><<<dim3(OUT_F / 64, HID_F / 64), 256>>>(W2);

    // GEMM1: H = relu(x @ W1 + b1) -> fp16 g_h
    gemm_kernel<0><<<dim3(HID_F / 128, BATCH / 128), 128, SMEM_DYN>>>(b1, nullptr);
    // GEMM2: out = sigmoid(H @ W2 + b2) -> f32 d_out
    gemm_kernel<1><<<dim3(OUT_F / 128, BATCH / 128), 128, SMEM_DYN>>>(b2, out);
}

// round 8
// speedup vs baseline: 1.0812x; 1.0812x over previous
#include <cuda_runtime.h>
#include <cuda_fp16.h>
#include <cstdint>
#include <cstddef>

// ---------------------------------------------------------------------------
// out = sigmoid(relu(x @ W1 + b1) @ W2 + b2)
// fp16 mma.sync (HMMA) GEMMs, fp32 accum, 2-stage cp.async pipeline.
// A consumed K-major (ldmatrix), B consumed [K,N]-major via ldmatrix.trans
// -> no weight transpose kernels, only streaming f32->f16 converts.
// (tcgen05 unavailable: harness PTX targets base sm_103, not sm_103a)
// ---------------------------------------------------------------------------

#define DI __device__ __forceinline__

static constexpr int BATCH = 4096;
static constexpr int IN_F  = 2048;
static constexpr int HID_F = 8192;
static constexpr int OUT_F = 2048;

__device__ __align__(16) __half g_x [(size_t)BATCH * IN_F];    // A1 [M,K]
__device__ __align__(16) __half g_w1[(size_t)IN_F  * HID_F];   // B1 [K,N]
__device__ __align__(16) __half g_w2[(size_t)HID_F * OUT_F];   // B2 [K,N]
__device__ __align__(16) __half g_h [(size_t)BATCH * HID_F];   // A2 [M,K]

// ---------------------------------------------------------------------------
DI uint32_t smem_u32(const void* p) {
    uint32_t a;
    asm("{ .reg .u64 t; cvta.to.shared.u64 t, %1; cvt.u32.u64 %0, t; }"
        : "=r"(a) : "l"(p));
    return a;
}

DI void cp_async16(uint32_t dst, const void* src) {
    asm volatile("cp.async.cg.shared.global [%0], [%1], 16;"
                 :: "r"(dst), "l"(src) : "memory");
}
DI void cp_commit() { asm volatile("cp.async.commit_group;" ::: "memory"); }
template <int N> DI void cp_wait() {
    asm volatile("cp.async.wait_group %0;" :: "n"(N) : "memory");
}

DI void ldm4(uint32_t* r, uint32_t addr) {
    asm volatile("ldmatrix.sync.aligned.m8n8.x4.shared.b16 {%0,%1,%2,%3}, [%4];"
                 : "=r"(r[0]), "=r"(r[1]), "=r"(r[2]), "=r"(r[3]) : "r"(addr));
}

DI void ldm4t(uint32_t* r, uint32_t addr) {
    asm volatile("ldmatrix.sync.aligned.m8n8.x4.trans.shared.b16 {%0,%1,%2,%3}, [%4];"
                 : "=r"(r[0]), "=r"(r[1]), "=r"(r[2]), "=r"(r[3]) : "r"(addr));
}

DI void mma16816(float* d, const uint32_t* a, uint32_t b0, uint32_t b1) {
    asm volatile(
        "mma.sync.aligned.m16n8k16.row.col.f32.f16.f16.f32 "
        "{%0,%1,%2,%3}, {%4,%5,%6,%7}, {%8,%9}, {%0,%1,%2,%3};"
        : "+f"(d[0]), "+f"(d[1]), "+f"(d[2]), "+f"(d[3])
        : "r"(a[0]), "r"(a[1]), "r"(a[2]), "r"(a[3]), "r"(b0), "r"(b1));
}

DI uint32_t sw128(uint32_t o) { return o ^ ((o >> 3) & 0x70); }

// ---------------------------------------------------------------------------
// Prep: pure streaming f32 -> f16 converts (no transposes)
// ---------------------------------------------------------------------------
template <int WHICH>   // 0: x->g_x, 1: W1->g_w1, 2: W2->g_w2
__global__ void convert_kernel(const float* __restrict__ src) {
    __half* dst = WHICH == 0 ? g_x : (WHICH == 1 ? g_w1 : g_w2);
    size_t i = ((size_t)blockIdx.x * 256 + threadIdx.x) * 8;
    float4 v0 = *reinterpret_cast<const float4*>(src + i);
    float4 v1 = *reinterpret_cast<const float4*>(src + i + 4);
    __half2 h[4];
    h[0] = __floats2half2_rn(v0.x, v0.y);
    h[1] = __floats2half2_rn(v0.z, v0.w);
    h[2] = __floats2half2_rn(v1.x, v1.y);
    h[3] = __floats2half2_rn(v1.z, v1.w);
    *reinterpret_cast<uint4*>(&dst[i]) = *reinterpret_cast<const uint4*>(h);
}

// ---------------------------------------------------------------------------
// GEMM: per-CTA 128x128, K-chunk 64, 2-stage cp.async pipeline.
// 256 threads = 8 warps as 4(M) x 2(N); warp tile 32x64 (best measured).
// A tile: 128 rows x 128B, SW128.  B tile: 64 k-rows x 272B (16B pad).
// ---------------------------------------------------------------------------
static constexpr int A_TILE   = 128 * 128;           // 16384
static constexpr int B_STRIDE = 272;                 // 128 fp16 + 8 pad
static constexpr int B_TILE   = 64 * B_STRIDE;       // 17408
static constexpr int STAGE_BYTES = A_TILE + B_TILE;  // 33792 (1024-multiple x33)
static constexpr int SMEM_DYN    = 1024 + 2 * STAGE_BYTES;

DI void load_tile_a(uint32_t sdst, const char* g, size_t ldb, int tid) {
    // 128 rows x 128B, SW128; 4 chunks/thread @256thr
#pragma unroll
    for (int i = 0; i < 4; ++i) {
        int idx = tid + i * 256;
        int row = idx >> 3;
        int c   = idx & 7;
        uint32_t o = (uint32_t)(row * 128 + c * 16);
        cp_async16(sdst + sw128(o), g + (size_t)row * ldb + c * 16);
    }
}

DI void load_tile_b(uint32_t sdst, const char* g, size_t ldb, int tid) {
    // 64 k-rows x 256B (16 chunks), padded stride 272; 4 chunks/thread @256thr
#pragma unroll
    for (int i = 0; i < 4; ++i) {
        int idx = tid + i * 256;          // 0..1023
        int row = idx >> 4;               // 0..63
        int c   = idx & 15;               // 0..15
        cp_async16(sdst + (uint32_t)(row * B_STRIDE + c * 16),
                   g + (size_t)row * ldb + c * 16);
    }
}

template <int EPI>
__global__ __launch_bounds__(256, 2)
void gemm_kernel(const float* __restrict__ bias, float* __restrict__ out_f32) {
    constexpr int KDIM  = EPI ? HID_F : IN_F;
    constexpr int NGLOB = EPI ? OUT_F : HID_F;
    constexpr int NITER = KDIM / 64;
    constexpr size_t LDA = (size_t)KDIM * 2;    // A row stride bytes
    constexpr size_t LDBN = (size_t)NGLOB * 2;  // B k-row stride bytes
    const __half* A = EPI ? g_h  : g_x;
    const __half* B = EPI ? g_w2 : g_w1;

    extern __shared__ char smem_raw[];
    const uint32_t sbase = (smem_u32(smem_raw) + 1023) & ~1023u;

    const int tid  = threadIdx.x;
    const int lane = tid & 31;
    const int warp = tid >> 5;
    const int wm   = warp & 3;    // 4 warps along M (32 rows each)
    const int wn   = warp >> 2;   // 2 warps along N (64 cols each)
    const int mBase = blockIdx.y * 128;
    const int nBase = blockIdx.x * 128;

    const char* gA = (const char*)(A + (size_t)mBase * KDIM);
    const char* gB = (const char*)(B + nBase);   // [K,N]: column offset only

    float acc[2][8][4];
#pragma unroll
    for (int i = 0; i < 2; ++i)
#pragma unroll
        for (int j = 0; j < 8; ++j)
#pragma unroll
            for (int k = 0; k < 4; ++k) acc[i][j][k] = 0.0f;

    // prologue: stage 0
    load_tile_a(sbase,          gA, LDA, tid);
    load_tile_b(sbase + A_TILE, gB, LDBN, tid);
    cp_commit();

    // A ldmatrix addressing (K-major, SW128): per warp two 16-row tiles
    const uint32_t aRowOff = (uint32_t)((wm * 32 + (lane & 15)) * 128 + ((lane >> 4) << 4));
    // B ldmatrix.trans addressing ([K,N], padded): thread t -> group q=t/8, r=t%8
    //   k = (q&1)*8 + r, n = wn*64 + nblk*16 + (q>>1)*8
    const int q = lane >> 3, r = lane & 7;
    const uint32_t bAddrBase = (uint32_t)(((q & 1) * 8 + r) * B_STRIDE
                                          + (wn * 64 + (q >> 1) * 8) * 2);

#pragma unroll 1
    for (int it = 0; it < NITER; ++it) {
        __syncthreads();
        if (it + 1 < NITER) {
            const uint32_t sNext = sbase + ((it + 1) & 1) * STAGE_BYTES;
            load_tile_a(sNext,          gA + (size_t)(it + 1) * 128, LDA, tid);
            load_tile_b(sNext + A_TILE, gB + (size_t)(it + 1) * 64 * LDBN, LDBN, tid);
            cp_commit();
            cp_wait<1>();
        } else {
            cp_wait<0>();
        }
        __syncthreads();

        const uint32_t As = sbase + (it & 1) * STAGE_BYTES;
        const uint32_t Bs = As + A_TILE;

#pragma unroll
        for (int ks = 0; ks < 4; ++ks) {
            uint32_t a[2][4], b[4][4];
#pragma unroll
            for (int mt = 0; mt < 2; ++mt)
                ldm4(a[mt], As + sw128(aRowOff + mt * 16 * 128 + ks * 32));
            // B: 4 trans-groups, each covering k16 x n16 at this ks
            const uint32_t bs = Bs + bAddrBase + (uint32_t)(ks * 16 * B_STRIDE);
#pragma unroll
            for (int nb = 0; nb < 4; ++nb)
                ldm4t(b[nb], bs + nb * 32);   // +16 cols = 32 bytes
#pragma unroll
            for (int mt = 0; mt < 2; ++mt)
#pragma unroll
                for (int nt = 0; nt < 8; ++nt) {
                    const uint32_t* bb = b[nt >> 1];
                    // even n8: (r0,r1); odd n8: (r2,r3)
                    if (nt & 1) mma16816(acc[mt][nt], a[mt], bb[2], bb[3]);
                    else        mma16816(acc[mt][nt], a[mt], bb[0], bb[1]);
                }
        }
    }

    // epilogue
#pragma unroll
    for (int mt = 0; mt < 2; ++mt) {
#pragma unroll
        for (int nt = 0; nt < 8; ++nt) {
            const int col = nBase + wn * 64 + nt * 8 + (lane & 3) * 2;
            const float bv0 = __ldg(&bias[col]);
            const float bv1 = __ldg(&bias[col + 1]);
#pragma unroll
            for (int rr = 0; rr < 2; ++rr) {
                const int row = mBase + wm * 32 + mt * 16 + (lane >> 2) + rr * 8;
                float v0 = acc[mt][nt][rr * 2 + 0] + bv0;
                float v1 = acc[mt][nt][rr * 2 + 1] + bv1;
                if (EPI == 0) {
                    __half2 h = __floats2half2_rn(fmaxf(v0, 0.0f), fmaxf(v1, 0.0f));
                    *reinterpret_cast<__half2*>(&g_h[(size_t)row * HID_F + col]) = h;
                } else {
                    float2 o;
                    o.x = 1.0f / (1.0f + __expf(-v0));
                    o.y = 1.0f / (1.0f + __expf(-v1));
                    *reinterpret_cast<float2*>(&out_f32[(size_t)row * OUT_F + col]) = o;
                }
            }
        }
    }
}

// ---------------------------------------------------------------------------
extern "C" void kernel_launch(void* const* d_in, const int* in_sizes, int n_in,
                              void* d_out, int out_size) {
    (void)in_sizes; (void)n_in; (void)out_size;
    const float* x  = (const float*)d_in[0];
    const float* W1 = (const float*)d_in[1];
    const float* b1 = (const float*)d_in[2];
    const float* W2 = (const float*)d_in[3];
    const float* b2 = (const float*)d_in[4];
    float* out = (float*)d_out;

    cudaFuncSetAttribute(gemm_kernel<0>, cudaFuncAttributeMaxDynamicSharedMemorySize, SMEM_DYN);
    cudaFuncSetAttribute(gemm_kernel<1>, cudaFuncAttributeMaxDynamicSharedMemorySize, SMEM_DYN);

    convert_kernel<0><<<(BATCH * IN_F)  / (256 * 8), 256>>>(x);
    convert_kernel<1><<<(IN_F * HID_F)  / (256 * 8), 256>>>(W1);
    convert_kernel<2><<<(HID_F * OUT_F) / (256 * 8), 256>>>(W2);

    // GEMM1: H = relu(x @ W1 + b1) -> fp16 g_h
    gemm_kernel<0><<<dim3(HID_F / 128, BATCH / 128), 256, SMEM_DYN>>>(b1, nullptr);
    // GEMM2: out = sigmoid(H @ W2 + b2) -> f32 d_out
    gemm_kernel<1><<<dim3(OUT_F / 128, BATCH / 128), 256, SMEM_DYN>>>(b2, out);
}